// round 16
// baseline (speedup 1.0000x reference)
#include <cuda_runtime.h>

#define N_NODES 50000
#define N_EDGES 600000
#define D 128
#define BN_EPS 1e-5f

// ---------------- scratch (static device globals; no runtime alloc) ----------
__device__ float  g_agg0[(size_t)N_NODES * D];   // replica 0
__device__ float  g_agg1[(size_t)N_NODES * D];   // replica 1
__device__ double g_sum[D];
__device__ double g_sumsq[D];

// ---------------- kernel 1: zero aggs + BN accumulators ---------------------
__global__ void zero_kernel() {
    long long i = (long long)blockIdx.x * blockDim.x + threadIdx.x;
    const long long n4 = (long long)N_NODES * D / 4;
    if (i < n4) {
        reinterpret_cast<float4*>(g_agg0)[i] = make_float4(0.f, 0.f, 0.f, 0.f);
        reinterpret_cast<float4*>(g_agg1)[i] = make_float4(0.f, 0.f, 0.f, 0.f);
    }
    if (i < D) { g_sum[i] = 0.0; g_sumsq[i] = 0.0; }
}

// ---------------- kernel 2: edge scatter (1 warp per 4 edges) ---------------
__global__ void edge_kernel(const float* __restrict__ x,
                            const int*   __restrict__ ei,
                            const float* __restrict__ ea) {
    int warp = (blockIdx.x * blockDim.x + threadIdx.x) >> 5;
    int lane = threadIdx.x & 31;
    if (warp >= N_EDGES / 4) return;
    int4 s4 = *reinterpret_cast<const int4*>(ei + 4 * warp);
    int4 d4 = *reinterpret_cast<const int4*>(ei + N_EDGES + 4 * warp);
    const float4* __restrict__ x4  = reinterpret_cast<const float4*>(x);
    const float4* __restrict__ ea4 = reinterpret_cast<const float4*>(ea);

    float4 xa = x4[(long long)s4.x * 32 + lane];
    float4 e0 = ea4[(long long)(4 * warp + 0) * 32 + lane];
    float4 xb = x4[(long long)s4.y * 32 + lane];
    float4 e1 = ea4[(long long)(4 * warp + 1) * 32 + lane];
    float4 xc = x4[(long long)s4.z * 32 + lane];
    float4 e2 = ea4[(long long)(4 * warp + 2) * 32 + lane];
    float4 xd = x4[(long long)s4.w * 32 + lane];
    float4 e3 = ea4[(long long)(4 * warp + 3) * 32 + lane];

    float4 m0, m1, m2, m3;
    m0.x = fmaxf(xa.x + e0.x, 0.f); m0.y = fmaxf(xa.y + e0.y, 0.f);
    m0.z = fmaxf(xa.z + e0.z, 0.f); m0.w = fmaxf(xa.w + e0.w, 0.f);
    m1.x = fmaxf(xb.x + e1.x, 0.f); m1.y = fmaxf(xb.y + e1.y, 0.f);
    m1.z = fmaxf(xb.z + e1.z, 0.f); m1.w = fmaxf(xb.w + e1.w, 0.f);
    m2.x = fmaxf(xc.x + e2.x, 0.f); m2.y = fmaxf(xc.y + e2.y, 0.f);
    m2.z = fmaxf(xc.z + e2.z, 0.f); m2.w = fmaxf(xc.w + e2.w, 0.f);
    m3.x = fmaxf(xd.x + e3.x, 0.f); m3.y = fmaxf(xd.y + e3.y, 0.f);
    m3.z = fmaxf(xd.z + e3.z, 0.f); m3.w = fmaxf(xd.w + e3.w, 0.f);

    float* p0 = g_agg0 + (long long)d4.x * D + lane * 4;
    float* p1 = g_agg1 + (long long)d4.y * D + lane * 4;
    float* p2 = g_agg0 + (long long)d4.z * D + lane * 4;
    float* p3 = g_agg1 + (long long)d4.w * D + lane * 4;
    asm volatile("red.global.add.v4.f32 [%0], {%1, %2, %3, %4};"
                 :: "l"(p0), "f"(m0.x), "f"(m0.y), "f"(m0.z), "f"(m0.w) : "memory");
    asm volatile("red.global.add.v4.f32 [%0], {%1, %2, %3, %4};"
                 :: "l"(p1), "f"(m1.x), "f"(m1.y), "f"(m1.z), "f"(m1.w) : "memory");
    asm volatile("red.global.add.v4.f32 [%0], {%1, %2, %3, %4};"
                 :: "l"(p2), "f"(m2.x), "f"(m2.y), "f"(m2.z), "f"(m2.w) : "memory");
    asm volatile("red.global.add.v4.f32 [%0], {%1, %2, %3, %4};"
                 :: "l"(p3), "f"(m3.x), "f"(m3.y), "f"(m3.z), "f"(m3.w) : "memory");
}

// ---------------- kernel 3: fused MLP, 128-row tiles, 512 threads -----------
#define SM_STRIDE 132
#define GEMM_SMEM (2 * 128 * SM_STRIDE * 4)

__global__ void __launch_bounds__(512, 1)
fused_mlp(const float* __restrict__ x,
          const float* __restrict__ W1,
          const float* __restrict__ bias1,
          const float* __restrict__ W2,
          const float* __restrict__ bias2,
          float* __restrict__ out) {
    extern __shared__ float sh[];
    float* bufA = sh;                        // W1^T, then h1^T (swizzled)
    float* bufB = sh + 128 * SM_STRIDE;      // h0 tile, then W2^T
    const int t = threadIdx.x;
    const int row0 = blockIdx.x * 128;

    // load W1 transposed: bufA[k*132 + o] = W1[o][k]
#pragma unroll
    for (int i = 0; i < 32; i++) {
        int idx = i * 512 + t;
        int o = idx >> 7, k = idx & 127;
        bufA[k * SM_STRIDE + o] = W1[o * 128 + k];
    }
    // load h0 tile transposed: bufB[k*132 + r] = x + agg0 + agg1
#pragma unroll
    for (int i = 0; i < 32; i++) {
        int idx = i * 512 + t;
        int r = idx >> 7, k = idx & 127;
        int row = row0 + r;
        float v = 0.f;
        if (row < N_NODES) {
            long long g = (long long)row * 128 + k;
            v = x[g] + g_agg0[g] + g_agg1[g];
        }
        bufB[k * SM_STRIDE + r] = v;
    }
    __syncthreads();

    const int tx = t & 15, ty = t >> 4;      // 16 col-groups x 32 row-groups
    const int c0 = tx * 8, r0 = ty * 4;
    float acc[4][8];
#pragma unroll
    for (int i = 0; i < 4; i++)
#pragma unroll
        for (int j = 0; j < 8; j++) acc[i][j] = 0.f;

    // ---- phase 1: acc = h0_tile @ W1^T ----
#pragma unroll 4
    for (int k = 0; k < 128; k++) {
        float4 a0 = *reinterpret_cast<const float4*>(bufB + k * SM_STRIDE + r0);
        const float4* wp = reinterpret_cast<const float4*>(bufA + k * SM_STRIDE + c0);
        float4 b0 = wp[0], b1 = wp[1];
        float av[4] = {a0.x, a0.y, a0.z, a0.w};
        float bv[8] = {b0.x, b0.y, b0.z, b0.w, b1.x, b1.y, b1.z, b1.w};
#pragma unroll
        for (int i = 0; i < 4; i++)
#pragma unroll
            for (int j = 0; j < 8; j++) acc[i][j] += av[i] * bv[j];
    }

    float bb[8];
#pragma unroll
    for (int j = 0; j < 8; j++) bb[j] = bias1[c0 + j];
    __syncthreads();   // all reads of bufA/bufB done

    // ---- store h1^T (relu) into bufA, swizzled: elem r -> col (r ^ 4*((k2>>3)&7))
#pragma unroll
    for (int j = 0; j < 8; j++) {
        int k2 = c0 + j;
        int swz = ((k2 >> 3) & 7) << 2;
#pragma unroll
        for (int i = 0; i < 4; i++) {
            int r = r0 + i;
            bufA[k2 * 128 + (r ^ swz)] = fmaxf(acc[i][j] + bb[j], 0.f);
        }
    }
    // ---- load W2 transposed into bufB ----
#pragma unroll
    for (int i = 0; i < 32; i++) {
        int idx = i * 512 + t;
        int o = idx >> 7, k = idx & 127;
        bufB[k * SM_STRIDE + o] = W2[o * 128 + k];
    }
    __syncthreads();

    // ---- phase 2: acc = h1 @ W2^T ----
#pragma unroll
    for (int i = 0; i < 4; i++)
#pragma unroll
        for (int j = 0; j < 8; j++) acc[i][j] = 0.f;

#pragma unroll 4
    for (int k = 0; k < 128; k++) {
        int swz = ((k >> 3) & 7) << 2;
        float4 a0 = *reinterpret_cast<const float4*>(bufA + k * 128 + (r0 ^ swz));
        const float4* wp = reinterpret_cast<const float4*>(bufB + k * SM_STRIDE + c0);
        float4 b0 = wp[0], b1 = wp[1];
        float av[4] = {a0.x, a0.y, a0.z, a0.w};
        float bv[8] = {b0.x, b0.y, b0.z, b0.w, b1.x, b1.y, b1.z, b1.w};
#pragma unroll
        for (int i = 0; i < 4; i++)
#pragma unroll
            for (int j = 0; j < 8; j++) acc[i][j] += av[i] * bv[j];
    }

#pragma unroll
    for (int j = 0; j < 8; j++) bb[j] = bias2[c0 + j];

    // ---- epilogue: write out + per-block BN column partials ----
    float cs[8], css[8];
#pragma unroll
    for (int j = 0; j < 8; j++) { cs[j] = 0.f; css[j] = 0.f; }

#pragma unroll
    for (int i = 0; i < 4; i++) {
        int row = row0 + r0 + i;
        if (row < N_NODES) {
            float o[8];
#pragma unroll
            for (int j = 0; j < 8; j++) {
                float v = acc[i][j] + bb[j];
                o[j] = v;
                cs[j] += v;
                css[j] += v * v;
            }
            float* dst = out + (long long)row * 128 + c0;
            reinterpret_cast<float4*>(dst)[0] = make_float4(o[0], o[1], o[2], o[3]);
            reinterpret_cast<float4*>(dst)[1] = make_float4(o[4], o[5], o[6], o[7]);
        }
    }

    __syncthreads();   // compute reads done; reuse smem for stat reduction
    float* redS  = sh;                 // [32][128]
    float* redSS = sh + 32 * 128;      // [32][128]
#pragma unroll
    for (int j = 0; j < 8; j++) {
        redS [ty * 128 + c0 + j] = cs[j];
        redSS[ty * 128 + c0 + j] = css[j];
    }
    __syncthreads();
    if (t < 128) {
        double s = 0.0, ss = 0.0;
#pragma unroll
        for (int q = 0; q < 32; q++) {
            s  += (double)redS [q * 128 + t];
            ss += (double)redSS[q * 128 + t];
        }
        atomicAdd(&g_sum[t], s);
        atomicAdd(&g_sumsq[t], ss);
    }
}

// ---------------- kernel 4: BN normalize + relu (inline scale/shift) --------
__global__ void bn_finalize(float* __restrict__ h,
                            const float* __restrict__ w,
                            const float* __restrict__ b) {
    __shared__ float s_scale[D];
    __shared__ float s_shift[D];
    if (threadIdx.x < D) {
        int c = threadIdx.x;
        const double invN = 1.0 / (double)N_NODES;
        double mean = g_sum[c] * invN;
        double var  = g_sumsq[c] * invN - mean * mean;
        float rstd = rsqrtf((float)var + BN_EPS);
        float sc = w[c] * rstd;
        s_scale[c] = sc;
        s_shift[c] = b[c] - (float)mean * sc;
    }
    __syncthreads();
    long long i = (long long)blockIdx.x * blockDim.x + threadIdx.x;
    const long long n4 = (long long)N_NODES * D / 4;
    if (i >= n4) return;
    int c0 = (int)(i & 31) * 4;
    float4 v = reinterpret_cast<float4*>(h)[i];
    float4 sc = *reinterpret_cast<const float4*>(s_scale + c0);
    float4 sf = *reinterpret_cast<const float4*>(s_shift + c0);
    float4 o;
    o.x = fmaxf(fmaf(v.x, sc.x, sf.x), 0.f);
    o.y = fmaxf(fmaf(v.y, sc.y, sf.y), 0.f);
    o.z = fmaxf(fmaf(v.z, sc.z, sf.z), 0.f);
    o.w = fmaxf(fmaf(v.w, sc.w, sf.w), 0.f);
    reinterpret_cast<float4*>(h)[i] = o;
}

// ---------------- launcher ---------------------------------------------------
extern "C" void kernel_launch(void* const* d_in, const int* in_sizes, int n_in,
                              void* d_out, int out_size) {
    const float* x   = (const float*)d_in[0];
    const int*   ei  = (const int*)  d_in[1];
    const float* ea  = (const float*)d_in[2];
    const float* w1  = (const float*)d_in[3];
    const float* b1  = (const float*)d_in[4];
    const float* w2  = (const float*)d_in[5];
    const float* b2  = (const float*)d_in[6];
    const float* bnw = (const float*)d_in[7];
    const float* bnb = (const float*)d_in[8];
    float* out = (float*)d_out;

    cudaFuncSetAttribute(fused_mlp, cudaFuncAttributeMaxDynamicSharedMemorySize, GEMM_SMEM);

    // 1. zero scratch (both replicas + BN sums)
    zero_kernel<<<(N_NODES * D / 4 + 255) / 256, 256>>>();
    // 2. edge scatter: one warp per 4 edges, replica alternates by edge parity
    {
        long long threads = (long long)(N_EDGES / 4) * 32;
        edge_kernel<<<(unsigned)((threads + 255) / 256), 256>>>(x, ei, ea);
    }
    // 3. fused MLP (both linears + BN stats), 128-row tiles, 512 threads
    const int ntiles = (N_NODES + 127) / 128;
    fused_mlp<<<ntiles, 512, GEMM_SMEM>>>(x, w1, b1, w2, b2, out);
    // 4. normalize + relu in place (scale/shift derived in-kernel)
    bn_finalize<<<(N_NODES * D / 4 + 255) / 256, 256>>>(out, bnw, bnb);
}

// round 17
// speedup vs baseline: 1.3970x; 1.3970x over previous
#include <cuda_runtime.h>

#define N_NODES 50000
#define N_EDGES 600000
#define D 128
#define BN_EPS 1e-5f

// ---------------- scratch (static device globals; no runtime alloc) ----------
__device__ float  g_agg0[(size_t)N_NODES * D];   // replica 0
__device__ float  g_agg1[(size_t)N_NODES * D];   // replica 1
__device__ double g_sum[D];
__device__ double g_sumsq[D];

// ---------------- kernel 1: zero aggs + BN accumulators ---------------------
__global__ void zero_kernel() {
    long long i = (long long)blockIdx.x * blockDim.x + threadIdx.x;
    const long long n4 = (long long)N_NODES * D / 4;
    if (i < n4) {
        reinterpret_cast<float4*>(g_agg0)[i] = make_float4(0.f, 0.f, 0.f, 0.f);
        reinterpret_cast<float4*>(g_agg1)[i] = make_float4(0.f, 0.f, 0.f, 0.f);
    }
    if (i < D) { g_sum[i] = 0.0; g_sumsq[i] = 0.0; }
}

// ---------------- kernel 2: edge scatter (1 warp per 4 edges) ---------------
__global__ void edge_kernel(const float* __restrict__ x,
                            const int*   __restrict__ ei,
                            const float* __restrict__ ea) {
    int warp = (blockIdx.x * blockDim.x + threadIdx.x) >> 5;
    int lane = threadIdx.x & 31;
    if (warp >= N_EDGES / 4) return;
    int4 s4 = *reinterpret_cast<const int4*>(ei + 4 * warp);
    int4 d4 = *reinterpret_cast<const int4*>(ei + N_EDGES + 4 * warp);
    const float4* __restrict__ x4  = reinterpret_cast<const float4*>(x);
    const float4* __restrict__ ea4 = reinterpret_cast<const float4*>(ea);

    float4 xa = x4[(long long)s4.x * 32 + lane];
    float4 e0 = ea4[(long long)(4 * warp + 0) * 32 + lane];
    float4 xb = x4[(long long)s4.y * 32 + lane];
    float4 e1 = ea4[(long long)(4 * warp + 1) * 32 + lane];
    float4 xc = x4[(long long)s4.z * 32 + lane];
    float4 e2 = ea4[(long long)(4 * warp + 2) * 32 + lane];
    float4 xd = x4[(long long)s4.w * 32 + lane];
    float4 e3 = ea4[(long long)(4 * warp + 3) * 32 + lane];

    float4 m0, m1, m2, m3;
    m0.x = fmaxf(xa.x + e0.x, 0.f); m0.y = fmaxf(xa.y + e0.y, 0.f);
    m0.z = fmaxf(xa.z + e0.z, 0.f); m0.w = fmaxf(xa.w + e0.w, 0.f);
    m1.x = fmaxf(xb.x + e1.x, 0.f); m1.y = fmaxf(xb.y + e1.y, 0.f);
    m1.z = fmaxf(xb.z + e1.z, 0.f); m1.w = fmaxf(xb.w + e1.w, 0.f);
    m2.x = fmaxf(xc.x + e2.x, 0.f); m2.y = fmaxf(xc.y + e2.y, 0.f);
    m2.z = fmaxf(xc.z + e2.z, 0.f); m2.w = fmaxf(xc.w + e2.w, 0.f);
    m3.x = fmaxf(xd.x + e3.x, 0.f); m3.y = fmaxf(xd.y + e3.y, 0.f);
    m3.z = fmaxf(xd.z + e3.z, 0.f); m3.w = fmaxf(xd.w + e3.w, 0.f);

    float* p0 = g_agg0 + (long long)d4.x * D + lane * 4;
    float* p1 = g_agg1 + (long long)d4.y * D + lane * 4;
    float* p2 = g_agg0 + (long long)d4.z * D + lane * 4;
    float* p3 = g_agg1 + (long long)d4.w * D + lane * 4;
    asm volatile("red.global.add.v4.f32 [%0], {%1, %2, %3, %4};"
                 :: "l"(p0), "f"(m0.x), "f"(m0.y), "f"(m0.z), "f"(m0.w) : "memory");
    asm volatile("red.global.add.v4.f32 [%0], {%1, %2, %3, %4};"
                 :: "l"(p1), "f"(m1.x), "f"(m1.y), "f"(m1.z), "f"(m1.w) : "memory");
    asm volatile("red.global.add.v4.f32 [%0], {%1, %2, %3, %4};"
                 :: "l"(p2), "f"(m2.x), "f"(m2.y), "f"(m2.z), "f"(m2.w) : "memory");
    asm volatile("red.global.add.v4.f32 [%0], {%1, %2, %3, %4};"
                 :: "l"(p3), "f"(m3.x), "f"(m3.y), "f"(m3.z), "f"(m3.w) : "memory");
}

// ---------------- kernel 3: fused MLP (R12 geometry: 256 thr, 8x8) ----------
#define SM_STRIDE 132
#define GEMM_SMEM (2 * 128 * SM_STRIDE * 4)

__global__ void fused_mlp(const float* __restrict__ x,
                          const float* __restrict__ W1,
                          const float* __restrict__ bias1,
                          const float* __restrict__ W2,
                          const float* __restrict__ bias2,
                          float* __restrict__ out) {
    extern __shared__ float sh[];
    float* bufA = sh;                        // W1^T, then h1^T (swizzled)
    float* bufB = sh + 128 * SM_STRIDE;      // h0 tile, then W2^T
    const int t = threadIdx.x;
    const int row0 = blockIdx.x * 128;

#pragma unroll
    for (int i = 0; i < 64; i++) {
        int idx = i * 256 + t;
        int o = idx >> 7, k = idx & 127;
        bufA[k * SM_STRIDE + o] = W1[o * 128 + k];
    }
#pragma unroll
    for (int i = 0; i < 64; i++) {
        int idx = i * 256 + t;
        int r = idx >> 7, k = idx & 127;
        int row = row0 + r;
        float v = 0.f;
        if (row < N_NODES) {
            long long g = (long long)row * 128 + k;
            v = x[g] + g_agg0[g] + g_agg1[g];
        }
        bufB[k * SM_STRIDE + r] = v;
    }
    __syncthreads();

    const int tx = t & 15, ty = t >> 4;
    const int c0 = tx * 8, r0 = ty * 8;
    float acc[8][8];
#pragma unroll
    for (int i = 0; i < 8; i++)
#pragma unroll
        for (int j = 0; j < 8; j++) acc[i][j] = 0.f;

    // ---- phase 1: acc = h0_tile @ W1^T ----
#pragma unroll 4
    for (int k = 0; k < 128; k++) {
        const float4* hp = reinterpret_cast<const float4*>(bufB + k * SM_STRIDE + r0);
        const float4* wp = reinterpret_cast<const float4*>(bufA + k * SM_STRIDE + c0);
        float4 a0 = hp[0], a1 = hp[1];
        float4 b0 = wp[0], b1 = wp[1];
        float av[8] = {a0.x, a0.y, a0.z, a0.w, a1.x, a1.y, a1.z, a1.w};
        float bv[8] = {b0.x, b0.y, b0.z, b0.w, b1.x, b1.y, b1.z, b1.w};
#pragma unroll
        for (int i = 0; i < 8; i++)
#pragma unroll
            for (int j = 0; j < 8; j++) acc[i][j] += av[i] * bv[j];
    }

    float bb[8];
#pragma unroll
    for (int j = 0; j < 8; j++) bb[j] = bias1[c0 + j];
    __syncthreads();

    // ---- store h1^T (relu) swizzled: elem r -> col (r ^ 4*((k2>>3)&7))
#pragma unroll
    for (int j = 0; j < 8; j++) {
        int k2 = c0 + j;
        int swz = ((k2 >> 3) & 7) << 2;
#pragma unroll
        for (int i = 0; i < 8; i++) {
            int r = r0 + i;
            bufA[k2 * 128 + (r ^ swz)] = fmaxf(acc[i][j] + bb[j], 0.f);
        }
    }
#pragma unroll
    for (int i = 0; i < 64; i++) {
        int idx = i * 256 + t;
        int o = idx >> 7, k = idx & 127;
        bufB[k * SM_STRIDE + o] = W2[o * 128 + k];
    }
    __syncthreads();

    // ---- phase 2: acc = h1 @ W2^T ----
#pragma unroll
    for (int i = 0; i < 8; i++)
#pragma unroll
        for (int j = 0; j < 8; j++) acc[i][j] = 0.f;

#pragma unroll 4
    for (int k = 0; k < 128; k++) {
        int swz = ((k >> 3) & 7) << 2;
        float4 a0 = *reinterpret_cast<const float4*>(bufA + k * 128 + (r0 ^ swz));
        float4 a1 = *reinterpret_cast<const float4*>(bufA + k * 128 + ((r0 + 4) ^ swz));
        const float4* wp = reinterpret_cast<const float4*>(bufB + k * SM_STRIDE + c0);
        float4 b0 = wp[0], b1 = wp[1];
        float av[8] = {a0.x, a0.y, a0.z, a0.w, a1.x, a1.y, a1.z, a1.w};
        float bv[8] = {b0.x, b0.y, b0.z, b0.w, b1.x, b1.y, b1.z, b1.w};
#pragma unroll
        for (int i = 0; i < 8; i++)
#pragma unroll
            for (int j = 0; j < 8; j++) acc[i][j] += av[i] * bv[j];
    }

#pragma unroll
    for (int j = 0; j < 8; j++) bb[j] = bias2[c0 + j];

    float cs[8], css[8];
#pragma unroll
    for (int j = 0; j < 8; j++) { cs[j] = 0.f; css[j] = 0.f; }

#pragma unroll
    for (int i = 0; i < 8; i++) {
        int row = row0 + r0 + i;
        if (row < N_NODES) {
            float o[8];
#pragma unroll
            for (int j = 0; j < 8; j++) {
                float v = acc[i][j] + bb[j];
                o[j] = v;
                cs[j] += v;
                css[j] += v * v;
            }
            float* dst = out + (long long)row * 128 + c0;
            reinterpret_cast<float4*>(dst)[0] = make_float4(o[0], o[1], o[2], o[3]);
            reinterpret_cast<float4*>(dst)[1] = make_float4(o[4], o[5], o[6], o[7]);
        }
    }

    __syncthreads();
    float* redS  = sh;                 // [16][128]
    float* redSS = sh + 16 * 128;      // [16][128]
#pragma unroll
    for (int j = 0; j < 8; j++) {
        redS [ty * 128 + c0 + j] = cs[j];
        redSS[ty * 128 + c0 + j] = css[j];
    }
    __syncthreads();
    if (t < 128) {
        double s = 0.0, ss = 0.0;
#pragma unroll
        for (int q = 0; q < 16; q++) {
            s  += (double)redS [q * 128 + t];
            ss += (double)redSS[q * 128 + t];
        }
        atomicAdd(&g_sum[t], s);
        atomicAdd(&g_sumsq[t], ss);
    }
}

// ---------------- kernel 4: BN normalize + relu (inline scale/shift) --------
__global__ void bn_finalize(float* __restrict__ h,
                            const float* __restrict__ w,
                            const float* __restrict__ b) {
    __shared__ float s_scale[D];
    __shared__ float s_shift[D];
    if (threadIdx.x < D) {
        int c = threadIdx.x;
        const double invN = 1.0 / (double)N_NODES;
        double mean = g_sum[c] * invN;
        double var  = g_sumsq[c] * invN - mean * mean;
        float rstd = rsqrtf((float)var + BN_EPS);
        float sc = w[c] * rstd;
        s_scale[c] = sc;
        s_shift[c] = b[c] - (float)mean * sc;
    }
    __syncthreads();
    long long i = (long long)blockIdx.x * blockDim.x + threadIdx.x;
    const long long n4 = (long long)N_NODES * D / 4;
    if (i >= n4) return;
    int c0 = (int)(i & 31) * 4;
    float4 v = reinterpret_cast<float4*>(h)[i];
    float4 sc = *reinterpret_cast<const float4*>(s_scale + c0);
    float4 sf = *reinterpret_cast<const float4*>(s_shift + c0);
    float4 o;
    o.x = fmaxf(fmaf(v.x, sc.x, sf.x), 0.f);
    o.y = fmaxf(fmaf(v.y, sc.y, sf.y), 0.f);
    o.z = fmaxf(fmaf(v.z, sc.z, sf.z), 0.f);
    o.w = fmaxf(fmaf(v.w, sc.w, sf.w), 0.f);
    reinterpret_cast<float4*>(h)[i] = o;
}

// ---------------- launcher ---------------------------------------------------
extern "C" void kernel_launch(void* const* d_in, const int* in_sizes, int n_in,
                              void* d_out, int out_size) {
    const float* x   = (const float*)d_in[0];
    const int*   ei  = (const int*)  d_in[1];
    const float* ea  = (const float*)d_in[2];
    const float* w1  = (const float*)d_in[3];
    const float* b1  = (const float*)d_in[4];
    const float* w2  = (const float*)d_in[5];
    const float* b2  = (const float*)d_in[6];
    const float* bnw = (const float*)d_in[7];
    const float* bnb = (const float*)d_in[8];
    float* out = (float*)d_out;

    cudaFuncSetAttribute(fused_mlp, cudaFuncAttributeMaxDynamicSharedMemorySize, GEMM_SMEM);

    // 1. zero scratch (both replicas + BN sums)
    zero_kernel<<<(N_NODES * D / 4 + 255) / 256, 256>>>();
    // 2. edge scatter: one warp per 4 edges, replica alternates by edge parity
    {
        long long threads = (long long)(N_EDGES / 4) * 32;
        edge_kernel<<<(unsigned)((threads + 255) / 256), 256>>>(x, ei, ea);
    }
    // 3. fused MLP (both linears + BN stats), R12-proven geometry
    const int ntiles = (N_NODES + 127) / 128;
    fused_mlp<<<ntiles, 256, GEMM_SMEM>>>(x, w1, b1, w2, b2, out);
    // 4. normalize + relu in place (scale/shift derived in-kernel)
    bn_finalize<<<(N_NODES * D / 4 + 255) / 256, 256>>>(out, bnw, bnb);
}